// round 2
// baseline (speedup 1.0000x reference)
#include <cuda_runtime.h>
#include <cuda_bf16.h>
#include <stdint.h>

#define Bn  2
#define Nn  2048
#define Kn  48
#define Cn  128
#define INn 384
#define Hn  128

// ---------------- device scratch (no allocs allowed) ----------------
__device__ __nv_bfloat16 g_Wt1[Hn * INn];   // [n][k]  n<128, k<384
__device__ __nv_bfloat16 g_Wt2[Hn * Hn];    // [n][k]
__device__ __nv_bfloat16 g_Wt3[Cn * Hn];    // [n][k]
__device__ float g_u[Bn * Nn * Cn];         // LN1 output
__device__ int   g_is64;

// ---------------- helpers ----------------
__device__ __forceinline__ unsigned pk2(float a, float b) {
    __nv_bfloat162 t = __floats2bfloat162_rn(a, b);
    return *reinterpret_cast<unsigned*>(&t);
}

__device__ __forceinline__ float gelu_erf(float x) {
    return 0.5f * x * (1.0f + erff(x * 0.70710678118654752f));
}

__device__ __forceinline__ void mma16816(float c[4], const unsigned a[4], const unsigned b[2]) {
    asm volatile(
        "mma.sync.aligned.m16n8k16.row.col.f32.bf16.bf16.f32 "
        "{%0,%1,%2,%3},{%4,%5,%6,%7},{%8,%9},{%0,%1,%2,%3};"
        : "+f"(c[0]), "+f"(c[1]), "+f"(c[2]), "+f"(c[3])
        : "r"(a[0]), "r"(a[1]), "r"(a[2]), "r"(a[3]), "r"(b[0]), "r"(b[1]));
}

__device__ __forceinline__ void ldB4(unsigned bf[4][2], const __nv_bfloat16* base, int S,
                                     int nrow, int kofs) {
#pragma unroll
    for (int nt = 0; nt < 4; nt++) {
        const __nv_bfloat16* p = base + (nrow + nt * 8) * S + kofs;
        bf[nt][0] = *(const unsigned*)p;
        bf[nt][1] = *(const unsigned*)(p + 8);
    }
}

__device__ __forceinline__ void ldA4(unsigned af[4], const __nv_bfloat16* base, int S,
                                     int r, int kofs) {
    const __nv_bfloat16* p = base + r * S + kofs;
    af[0] = *(const unsigned*)p;
    af[1] = *(const unsigned*)(p + 8 * S);
    af[2] = *(const unsigned*)(p + 8);
    af[3] = *(const unsigned*)(p + 8 * S + 8);
}

// ---------------- prep: weight convert/transpose + idx dtype detect ----------------
__global__ void prep_kernel(const float* __restrict__ W1, const float* __restrict__ W2,
                            const float* __restrict__ W3, const unsigned* __restrict__ idxw) {
    int i = blockIdx.x * 256 + threadIdx.x;
    if (i < Hn * INn) {
        int nc = i / INn, k = i - nc * INn;
        g_Wt1[i] = __float2bfloat16_rn(W1[k * Hn + nc]);
    } else if (i < Hn * INn + Hn * Hn) {
        int j = i - Hn * INn;
        int nc = j >> 7, k = j & 127;
        g_Wt2[j] = __float2bfloat16_rn(W2[k * Hn + nc]);
    } else if (i < Hn * INn + 2 * Hn * Hn) {
        int j = i - Hn * INn - Hn * Hn;
        int nc = j >> 7, k = j & 127;
        g_Wt3[j] = __float2bfloat16_rn(W3[k * Cn + nc]);
    }
    if (blockIdx.x == 0 && threadIdx.x == 0) {
        // int64 data: high 32-bit words (odd u32 indices) are all zero.
        // int32 data: odd words are real indices in [0,2048); P(all 64 zero) ~ 0.
        int is64 = 1;
#pragma unroll 1
        for (int t = 1; t < 128; t += 2)
            if (idxw[t] != 0u) { is64 = 0; break; }
        g_is64 = is64;
    }
}

// ---------------- main: edge MLP + aggregate + LN1 ----------------
// grid = 2048 CTAs (2 nodes each), 256 threads (8 warps: wm in {0,1} x wn in {0..3})
// smem: sA[96][392] bf16 (75264) | sH[96][136] bf16 (26112) | sW[128][136] bf16 (34816)
//       | sMsg[2][128] f32 (1024)  => 137216 bytes
#define SMEM_MLP 137216

__global__ void __launch_bounds__(256, 1)
mlp_kernel(const float* __restrict__ node_h, const float* __restrict__ edge_h,
           const void* __restrict__ edge_index,
           const float* __restrict__ b1, const float* __restrict__ b2,
           const float* __restrict__ b3, const float* __restrict__ ln_g,
           const float* __restrict__ ln_b) {
    extern __shared__ char smem[];
    const int SA = 392, SH = 136, SW = 136;
    __nv_bfloat16* sA = (__nv_bfloat16*)smem;
    __nv_bfloat16* sH = (__nv_bfloat16*)(smem + 75264);
    __nv_bfloat16* sW = (__nv_bfloat16*)(smem + 75264 + 26112);
    float* sMsg = (float*)(smem + 75264 + 26112 + 34816);

    const int tid = threadIdx.x;
    const int lane = tid & 31, warp = tid >> 5;
    const int wm = warp >> 2, wn = warp & 3;
    const int g0 = blockIdx.x * 2;
    const int b = g0 >> 11;
    const int n0 = g0 & (Nn - 1);

    // ---- build edge_packed A tile [96 rows x 384 cols] in bf16 ----
    {
        const int is64 = g_is64;
        const long long* idx64 = (const long long*)edge_index;
        const int* idx32 = (const int*)edge_index;
#pragma unroll 1
        for (int i = tid; i < 96 * 96; i += 256) {
            int row = i / 96, s = i - row * 96;
            int sel = (row >= 48) ? 1 : 0;
            int e = row - sel * 48;
            int nn = n0 + sel;
            int c4 = s * 4;
            const float* src;
            if (c4 < 128) {
                src = node_h + ((b * Nn + nn) * Cn + c4);
            } else if (c4 < 256) {
                int ei = (b * Nn + nn) * Kn + e;
                int j = is64 ? (int)idx64[ei] : idx32[ei];
                src = node_h + ((b * Nn + j) * Cn + (c4 - 128));
            } else {
                src = edge_h + (((b * Nn + nn) * Kn + e) * Cn + (c4 - 256));
            }
            float4 v = *(const float4*)src;
            uint2 p;
            p.x = pk2(v.x, v.y);
            p.y = pk2(v.z, v.w);
            *(uint2*)(sA + row * SA + c4) = p;
        }
    }
    __syncthreads();

    float acc[3][4][4];
#pragma unroll
    for (int mt = 0; mt < 3; mt++)
#pragma unroll
        for (int nt = 0; nt < 4; nt++)
#pragma unroll
            for (int q = 0; q < 4; q++) acc[mt][nt][q] = 0.f;

    const int r0 = wm * 48 + (lane >> 2);
    const int cq = (lane & 3) * 2;
    const int nrow = wn * 32 + (lane >> 2);

    // ---- layer 1: [96,384] @ [384,128], K chunked by 64 through sW ----
#pragma unroll 1
    for (int ch = 0; ch < 6; ch++) {
        for (int i = tid; i < 128 * 8; i += 256) {
            int nr = i >> 3, kk = (i & 7) * 8;
            *(uint4*)(sW + nr * SW + kk) = *(const uint4*)(g_Wt1 + nr * INn + ch * 64 + kk);
        }
        __syncthreads();
#pragma unroll
        for (int kt = 0; kt < 4; kt++) {
            int kb = kt * 16;
            unsigned bf[4][2];
            ldB4(bf, sW, SW, nrow, kb + cq);
#pragma unroll
            for (int mt = 0; mt < 3; mt++) {
                unsigned af[4];
                ldA4(af, sA, SA, r0 + mt * 16, ch * 64 + kb + cq);
#pragma unroll
                for (int nt = 0; nt < 4; nt++) mma16816(acc[mt][nt], af, bf[nt]);
            }
        }
        __syncthreads();
    }
    // epilogue 1: +b1, gelu, -> sH (bf16)
#pragma unroll
    for (int mt = 0; mt < 3; mt++)
#pragma unroll
        for (int nt = 0; nt < 4; nt++) {
            int col = wn * 32 + nt * 8 + cq;
            float bb0 = b1[col], bb1 = b1[col + 1];
            int r = r0 + mt * 16;
            *(unsigned*)(sH + r * SH + col) =
                pk2(gelu_erf(acc[mt][nt][0] + bb0), gelu_erf(acc[mt][nt][1] + bb1));
            *(unsigned*)(sH + (r + 8) * SH + col) =
                pk2(gelu_erf(acc[mt][nt][2] + bb0), gelu_erf(acc[mt][nt][3] + bb1));
            acc[mt][nt][0] = acc[mt][nt][1] = acc[mt][nt][2] = acc[mt][nt][3] = 0.f;
        }
    // load full W2 into sW
    for (int i = tid; i < 128 * 16; i += 256) {
        int nr = i >> 4, kk = (i & 15) * 8;
        *(uint4*)(sW + nr * SW + kk) = *(const uint4*)(g_Wt2 + nr * Hn + kk);
    }
    __syncthreads();

    // ---- layer 2: [96,128] @ [128,128] ----
#pragma unroll 1
    for (int kt = 0; kt < 8; kt++) {
        int kb = kt * 16;
        unsigned bf[4][2];
        ldB4(bf, sW, SW, nrow, kb + cq);
#pragma unroll
        for (int mt = 0; mt < 3; mt++) {
            unsigned af[4];
            ldA4(af, sH, SH, r0 + mt * 16, kb + cq);
#pragma unroll
            for (int nt = 0; nt < 4; nt++) mma16816(acc[mt][nt], af, bf[nt]);
        }
    }
    __syncthreads();  // all h1 reads done before overwriting sH; all W2 reads before sW
    // epilogue 2: +b2, gelu, -> sH
#pragma unroll
    for (int mt = 0; mt < 3; mt++)
#pragma unroll
        for (int nt = 0; nt < 4; nt++) {
            int col = wn * 32 + nt * 8 + cq;
            float bb0 = b2[col], bb1 = b2[col + 1];
            int r = r0 + mt * 16;
            *(unsigned*)(sH + r * SH + col) =
                pk2(gelu_erf(acc[mt][nt][0] + bb0), gelu_erf(acc[mt][nt][1] + bb1));
            *(unsigned*)(sH + (r + 8) * SH + col) =
                pk2(gelu_erf(acc[mt][nt][2] + bb0), gelu_erf(acc[mt][nt][3] + bb1));
            acc[mt][nt][0] = acc[mt][nt][1] = acc[mt][nt][2] = acc[mt][nt][3] = 0.f;
        }
    // load W3 into sW
    for (int i = tid; i < 128 * 16; i += 256) {
        int nr = i >> 4, kk = (i & 15) * 8;
        *(uint4*)(sW + nr * SW + kk) = *(const uint4*)(g_Wt3 + nr * Hn + kk);
    }
    __syncthreads();

    // ---- layer 3: [96,128] @ [128,128] ----
#pragma unroll 1
    for (int kt = 0; kt < 8; kt++) {
        int kb = kt * 16;
        unsigned bf[4][2];
        ldB4(bf, sW, SW, nrow, kb + cq);
#pragma unroll
        for (int mt = 0; mt < 3; mt++) {
            unsigned af[4];
            ldA4(af, sH, SH, r0 + mt * 16, kb + cq);
#pragma unroll
            for (int nt = 0; nt < 4; nt++) mma16816(acc[mt][nt], af, bf[nt]);
        }
    }

    // ---- row-sum over K=48 edges (per node) ----
    float s0[4], s1[4];
#pragma unroll
    for (int nt = 0; nt < 4; nt++) {
        s0[nt] = acc[0][nt][0] + acc[0][nt][2] + acc[1][nt][0] + acc[1][nt][2] +
                 acc[2][nt][0] + acc[2][nt][2];
        s1[nt] = acc[0][nt][1] + acc[0][nt][3] + acc[1][nt][1] + acc[1][nt][3] +
                 acc[2][nt][1] + acc[2][nt][3];
    }
#pragma unroll
    for (int off = 4; off < 32; off <<= 1)
#pragma unroll
        for (int nt = 0; nt < 4; nt++) {
            s0[nt] += __shfl_xor_sync(0xffffffffu, s0[nt], off);
            s1[nt] += __shfl_xor_sync(0xffffffffu, s1[nt], off);
        }
    if (lane < 4) {
#pragma unroll
        for (int nt = 0; nt < 4; nt++) {
            int col = wn * 32 + nt * 8 + lane * 2;
            sMsg[wm * Cn + col] = s0[nt];
            sMsg[wm * Cn + col + 1] = s1[nt];
        }
    }
    __syncthreads();

    // ---- LN1 fused: u = LN(node_h + (sum + 48*b3)/30) -> g_u ----
    if (warp < 2) {
        int gg = g0 + warp;
        float x[4], sum = 0.f, sq = 0.f;
#pragma unroll
        for (int j = 0; j < 4; j++) {
            int col = lane + 32 * j;
            float m = (sMsg[warp * Cn + col] + 48.f * b3[col]) * (1.f / 30.f);
            x[j] = node_h[gg * Cn + col] + m;
            sum += x[j];
            sq += x[j] * x[j];
        }
#pragma unroll
        for (int off = 16; off; off >>= 1) {
            sum += __shfl_xor_sync(0xffffffffu, sum, off);
            sq += __shfl_xor_sync(0xffffffffu, sq, off);
        }
        float mean = sum * (1.f / Cn);
        float var = sq * (1.f / Cn) - mean * mean;
        float rs = rsqrtf(var + 1e-5f);
#pragma unroll
        for (int j = 0; j < 4; j++) {
            int col = lane + 32 * j;
            g_u[gg * Cn + col] = (x[j] - mean) * rs * ln_g[col] + ln_b[col];
        }
    }
}

// ---------------- final: out = LN(node_h + u@Wu + bu), fp32 ----------------
__global__ void __launch_bounds__(256)
final_kernel(const float* __restrict__ node_h, const float* __restrict__ Wu,
             const float* __restrict__ bu, const float* __restrict__ ln_g,
             const float* __restrict__ ln_b, float* __restrict__ out) {
    extern __shared__ float sWu[];  // 64 KB
    __shared__ float sU[8][128];
    int tid = threadIdx.x, lane = tid & 31, warp = tid >> 5;
    for (int i = tid; i < Cn * Cn; i += 256) sWu[i] = Wu[i];
    int g = blockIdx.x * 8 + warp;
#pragma unroll
    for (int j = 0; j < 4; j++) sU[warp][lane + 32 * j] = g_u[g * Cn + lane + 32 * j];
    __syncthreads();

    float y[4] = {0.f, 0.f, 0.f, 0.f};
#pragma unroll 4
    for (int k = 0; k < Cn; k++) {
        float uk = sU[warp][k];
#pragma unroll
        for (int j = 0; j < 4; j++) y[j] += uk * sWu[k * Cn + lane + 32 * j];
    }
    float x[4], sum = 0.f, sq = 0.f;
#pragma unroll
    for (int j = 0; j < 4; j++) {
        int col = lane + 32 * j;
        x[j] = node_h[g * Cn + col] + y[j] + bu[col];
        sum += x[j];
        sq += x[j] * x[j];
    }
#pragma unroll
    for (int off = 16; off; off >>= 1) {
        sum += __shfl_xor_sync(0xffffffffu, sum, off);
        sq += __shfl_xor_sync(0xffffffffu, sq, off);
    }
    float mean = sum * (1.f / Cn);
    float var = sq * (1.f / Cn) - mean * mean;
    float rs = rsqrtf(var + 1e-5f);
#pragma unroll
    for (int j = 0; j < 4; j++) {
        int col = lane + 32 * j;
        out[g * Cn + col] = (x[j] - mean) * rs * ln_g[col] + ln_b[col];
    }
}

// ---------------- launch ----------------
extern "C" void kernel_launch(void* const* d_in, const int* in_sizes, int n_in,
                              void* d_out, int out_size) {
    const float* node_h = (const float*)d_in[0];
    const float* edge_h = (const float*)d_in[1];
    const void* edge_index = d_in[2];
    const float* W1 = (const float*)d_in[3];
    const float* b1 = (const float*)d_in[4];
    const float* W2 = (const float*)d_in[5];
    const float* b2 = (const float*)d_in[6];
    const float* W3 = (const float*)d_in[7];
    const float* b3 = (const float*)d_in[8];
    const float* Wu = (const float*)d_in[9];
    const float* bu = (const float*)d_in[10];
    const float* ln_g = (const float*)d_in[11];
    const float* ln_b = (const float*)d_in[12];
    float* out = (float*)d_out;

    cudaFuncSetAttribute(mlp_kernel, cudaFuncAttributeMaxDynamicSharedMemorySize, SMEM_MLP);
    cudaFuncSetAttribute(final_kernel, cudaFuncAttributeMaxDynamicSharedMemorySize, 65536);

    prep_kernel<<<320, 256>>>(W1, W2, W3, (const unsigned*)edge_index);
    mlp_kernel<<<Bn * Nn / 2, 256, SMEM_MLP>>>(node_h, edge_h, edge_index,
                                               b1, b2, b3, ln_g, ln_b);
    final_kernel<<<Bn * Nn / 8, 256, 65536>>>(node_h, Wu, bu, ln_g, ln_b, out);
}

// round 4
// speedup vs baseline: 1.4772x; 1.4772x over previous
#include <cuda_runtime.h>
#include <cuda_bf16.h>
#include <stdint.h>

#define Bn 2
#define Nn 2048
#define Kn 48
#define Cn 128

// ---------------- device scratch ----------------
__device__ __nv_bfloat16 g_W1c[128 * 128];   // [n][k] = W1[256+k][n]
__device__ __nv_bfloat16 g_W2t[128 * 128];   // [n][k]
__device__ __nv_bfloat16 g_W3t[128 * 128];   // [n][k]
__device__ float g_Pi[Bn * Nn * Cn];         // node_h @ W1[0:128] + b1
__device__ float g_Pj[Bn * Nn * Cn];         // node_h @ W1[128:256]
__device__ float g_u[Bn * Nn * Cn];
__device__ int   g_is64;

// ---------------- helpers ----------------
__device__ __forceinline__ uint32_t smem_u32(const void* p) {
    uint32_t a;
    asm("{ .reg .u64 t; cvta.to.shared.u64 t, %1; cvt.u32.u64 %0, t; }" : "=r"(a) : "l"(p));
    return a;
}
__device__ __forceinline__ unsigned pk2(float a, float b) {
    __nv_bfloat162 t = __floats2bfloat162_rn(a, b);
    return *reinterpret_cast<unsigned*>(&t);
}
__device__ __forceinline__ float gelu_erf(float x) {
    return 0.5f * x * (1.0f + erff(x * 0.70710678118654752f));
}
__device__ __forceinline__ void mma16816(float c[4], const uint32_t a[4], const uint32_t b[2]) {
    asm volatile(
        "mma.sync.aligned.m16n8k16.row.col.f32.bf16.bf16.f32 "
        "{%0,%1,%2,%3},{%4,%5,%6,%7},{%8,%9},{%0,%1,%2,%3};"
        : "+f"(c[0]), "+f"(c[1]), "+f"(c[2]), "+f"(c[3])
        : "r"(a[0]), "r"(a[1]), "r"(a[2]), "r"(a[3]), "r"(b[0]), "r"(b[1]));
}
__device__ __forceinline__ void ldsm4(uint32_t r[4], uint32_t addr) {
    asm volatile("ldmatrix.sync.aligned.m8n8.x4.shared.b16 {%0,%1,%2,%3}, [%4];"
                 : "=r"(r[0]), "=r"(r[1]), "=r"(r[2]), "=r"(r[3]) : "r"(addr));
}

// ---------------- prep: weight transposes (bf16) + idx dtype detect ----------------
__global__ void prep_kernel(const float* __restrict__ W1, const float* __restrict__ W2,
                            const float* __restrict__ W3, const unsigned* __restrict__ idxw) {
    int i = blockIdx.x * 256 + threadIdx.x;
    if (i < 16384) {
        int n = i >> 7, k = i & 127;
        g_W1c[i] = __float2bfloat16_rn(W1[(256 + k) * 128 + n]);
    } else if (i < 32768) {
        int j = i - 16384, n = j >> 7, k = j & 127;
        g_W2t[j] = __float2bfloat16_rn(W2[k * 128 + n]);
    } else if (i < 49152) {
        int j = i - 32768, n = j >> 7, k = j & 127;
        g_W3t[j] = __float2bfloat16_rn(W3[k * 128 + n]);
    }
    if (blockIdx.x == 0 && threadIdx.x == 0) {
        int is64 = 1;
#pragma unroll 1
        for (int t = 1; t < 128; t += 2)
            if (idxw[t] != 0u) { is64 = 0; break; }
        g_is64 = is64;
    }
}

// ---------------- Pi/Pj precompute (fp32): 4096 rows, 128 CTAs x 32 rows ----------------
__global__ void __launch_bounds__(256)
pij_kernel(const float* __restrict__ node_h, const float* __restrict__ W1,
           const float* __restrict__ b1) {
    extern __shared__ float sw[];      // 128 KB: Wa | Wb
    float* sWa = sw;
    float* sWb = sw + 16384;
    int tid = threadIdx.x, lane = tid & 31, warp = tid >> 5;
    for (int i = tid; i < 16384; i += 256) {
        sWa[i] = W1[i];
        sWb[i] = W1[16384 + i];
    }
    __syncthreads();
#pragma unroll 1
    for (int it = 0; it < 4; it++) {
        int row = blockIdx.x * 32 + it * 8 + warp;
        const float4* nr = (const float4*)(node_h + (size_t)row * 128);
        float yi[4], yj[4];
#pragma unroll
        for (int j = 0; j < 4; j++) { yi[j] = b1[lane + 32 * j]; yj[j] = 0.f; }
#pragma unroll 4
        for (int k4 = 0; k4 < 32; k4++) {
            float4 x = nr[k4];
            int k = k4 * 4;
#pragma unroll
            for (int j = 0; j < 4; j++) {
                int c = lane + 32 * j;
                yi[j] += x.x * sWa[k * 128 + c] + x.y * sWa[(k + 1) * 128 + c] +
                         x.z * sWa[(k + 2) * 128 + c] + x.w * sWa[(k + 3) * 128 + c];
                yj[j] += x.x * sWb[k * 128 + c] + x.y * sWb[(k + 1) * 128 + c] +
                         x.z * sWb[(k + 2) * 128 + c] + x.w * sWb[(k + 3) * 128 + c];
            }
        }
#pragma unroll
        for (int j = 0; j < 4; j++) {
            g_Pi[(size_t)row * 128 + lane + 32 * j] = yi[j];
            g_Pj[(size_t)row * 128 + lane + 32 * j] = yj[j];
        }
    }
}

// ---------------- persistent edge-MLP kernel ----------------
// strides (elements): SA/SH=136 halves, SPQ=132 floats, SW=136 halves
#define SA  136
#define SPQ 132
#define SW  136
#define OFF_A   0
#define OFF_H   26112
#define OFF_PQ  52224
#define OFF_W1  102912
#define OFF_W2  137728
#define OFF_W3  172544
#define OFF_B2  207360
#define OFF_B3  207872
#define OFF_LG  208384
#define OFF_LB  208896
#define OFF_MSG 209408
#define SMEM_MLP 210432

__global__ void __launch_bounds__(256, 1)
mlp_kernel(const float* __restrict__ node_h, const float* __restrict__ edge_h,
           const void* __restrict__ edge_index, const float* __restrict__ b2,
           const float* __restrict__ b3, const float* __restrict__ ln_g,
           const float* __restrict__ ln_b) {
    extern __shared__ char smem[];
    const uint32_t sb = smem_u32(smem);
    float* sPQ = (float*)(smem + OFF_PQ);
    float* sB2 = (float*)(smem + OFF_B2);
    float* sB3 = (float*)(smem + OFF_B3);
    float* sLG = (float*)(smem + OFF_LG);
    float* sLB = (float*)(smem + OFF_LB);
    float* sMsg = (float*)(smem + OFF_MSG);

    const int tid = threadIdx.x, lane = tid & 31, warp = tid >> 5;
    const int wm = warp >> 2, wn = warp & 3;
    const int r0 = wm * 48;
    const int cq = (lane & 3) * 2;

    // stage weights once (resident for whole kernel)
    for (int i = tid; i < 128 * 16; i += 256) {
        int n = i >> 4, k = (i & 15) * 8;
        *(uint4*)(smem + OFF_W1 + (n * SW + k) * 2) = *(const uint4*)(g_W1c + n * 128 + k);
        *(uint4*)(smem + OFF_W2 + (n * SW + k) * 2) = *(const uint4*)(g_W2t + n * 128 + k);
        *(uint4*)(smem + OFF_W3 + (n * SW + k) * 2) = *(const uint4*)(g_W3t + n * 128 + k);
    }
    if (tid < 128) {
        sB2[tid] = b2[tid]; sB3[tid] = b3[tid];
        sLG[tid] = ln_g[tid]; sLB[tid] = ln_b[tid];
    }
    const int is64 = g_is64;
    const long long* idx64 = (const long long*)edge_index;
    const int* idx32 = (const int*)edge_index;
    __syncthreads();

    float acc[3][4][4];

    auto run_mma = [&](uint32_t aOff, uint32_t wOff) {
#pragma unroll
        for (int mt = 0; mt < 3; mt++)
#pragma unroll
            for (int nt = 0; nt < 4; nt++)
#pragma unroll
                for (int q = 0; q < 4; q++) acc[mt][nt][q] = 0.f;
#pragma unroll
        for (int kt = 0; kt < 8; kt++) {
            uint32_t rb[2][4];
#pragma unroll
            for (int j = 0; j < 2; j++)
                ldsm4(rb[j], sb + wOff +
                      ((wn * 32 + j * 16 + (lane & 15)) * SW + kt * 16 + (lane >> 4) * 8) * 2);
#pragma unroll
            for (int mt = 0; mt < 3; mt++) {
                uint32_t ra[4];
                ldsm4(ra, sb + aOff +
                      ((r0 + mt * 16 + (lane & 15)) * SA + kt * 16 + (lane >> 4) * 8) * 2);
#pragma unroll
                for (int j = 0; j < 2; j++)
#pragma unroll
                    for (int h = 0; h < 2; h++) {
                        uint32_t bbf[2] = { rb[j][h], rb[j][2 + h] };
                        mma16816(acc[mt][j * 2 + h], ra, bbf);
                    }
            }
        }
    };

#pragma unroll 1
    for (int t = blockIdx.x; t < Bn * Nn / 2; t += gridDim.x) {
        const int g0 = t * 2;
        const int bb = g0 >> 11;

        // ---- build: sA = bf16(edge_h rows), sPQ = Pi[center] + Pj[gathered] ----
        const float4* esrc = (const float4*)(edge_h + (size_t)g0 * Kn * Cn);
        const long long ib = (long long)g0 * Kn;
#pragma unroll 1
        for (int i = tid; i < 96 * 32; i += 256) {
            int row = i >> 5, c4 = (i & 31) << 2;
            float4 v = esrc[i];
            uint2 p; p.x = pk2(v.x, v.y); p.y = pk2(v.z, v.w);
            *(uint2*)(smem + OFF_A + (row * SA + c4) * 2) = p;
            int j = is64 ? (int)idx64[ib + row] : idx32[ib + row];
            int nn = g0 + (row >= 48 ? 1 : 0);
            float4 pi = *(const float4*)(g_Pi + (size_t)nn * 128 + c4);
            float4 pj = *(const float4*)(g_Pj + ((size_t)(bb * Nn) + j) * 128 + c4);
            float4 s;
            s.x = pi.x + pj.x; s.y = pi.y + pj.y; s.z = pi.z + pj.z; s.w = pi.w + pj.w;
            *(float4*)(sPQ + row * SPQ + c4) = s;
        }
        __syncthreads();

        // ---- layer 1 (K=128, edge part) + epi1: gelu(acc + PQ) -> sH ----
        run_mma(OFF_A, OFF_W1);
#pragma unroll
        for (int mt = 0; mt < 3; mt++) {
            int r = r0 + mt * 16 + (lane >> 2);
#pragma unroll
            for (int nt = 0; nt < 4; nt++) {
                int c = wn * 32 + nt * 8 + cq;
                const float* pq0 = sPQ + r * SPQ + c;
                const float* pq1 = sPQ + (r + 8) * SPQ + c;
                *(unsigned*)(smem + OFF_H + (r * SA + c) * 2) =
                    pk2(gelu_erf(acc[mt][nt][0] + pq0[0]), gelu_erf(acc[mt][nt][1] + pq0[1]));
                *(unsigned*)(smem + OFF_H + ((r + 8) * SA + c) * 2) =
                    pk2(gelu_erf(acc[mt][nt][2] + pq1[0]), gelu_erf(acc[mt][nt][3] + pq1[1]));
            }
        }
        __syncthreads();

        // ---- layer 2 + epi2: gelu(acc + b2) -> sA (reuse) ----
        run_mma(OFF_H, OFF_W2);
#pragma unroll
        for (int mt = 0; mt < 3; mt++) {
            int r = r0 + mt * 16 + (lane >> 2);
#pragma unroll
            for (int nt = 0; nt < 4; nt++) {
                int c = wn * 32 + nt * 8 + cq;
                float bb0 = sB2[c], bb1 = sB2[c + 1];
                *(unsigned*)(smem + OFF_A + (r * SA + c) * 2) =
                    pk2(gelu_erf(acc[mt][nt][0] + bb0), gelu_erf(acc[mt][nt][1] + bb1));
                *(unsigned*)(smem + OFF_A + ((r + 8) * SA + c) * 2) =
                    pk2(gelu_erf(acc[mt][nt][2] + bb0), gelu_erf(acc[mt][nt][3] + bb1));
            }
        }
        __syncthreads();

        // ---- layer 3 + aggregation over K=48 rows per node ----
        run_mma(OFF_A, OFF_W3);
        float s0[4], s1[4];
#pragma unroll
        for (int nt = 0; nt < 4; nt++) {
            s0[nt] = acc[0][nt][0] + acc[0][nt][2] + acc[1][nt][0] + acc[1][nt][2] +
                     acc[2][nt][0] + acc[2][nt][2];
            s1[nt] = acc[0][nt][1] + acc[0][nt][3] + acc[1][nt][1] + acc[1][nt][3] +
                     acc[2][nt][1] + acc[2][nt][3];
        }
#pragma unroll
        for (int off = 4; off < 32; off <<= 1)
#pragma unroll
            for (int nt = 0; nt < 4; nt++) {
                s0[nt] += __shfl_xor_sync(0xffffffffu, s0[nt], off);
                s1[nt] += __shfl_xor_sync(0xffffffffu, s1[nt], off);
            }
        if (lane < 4) {
#pragma unroll
            for (int nt = 0; nt < 4; nt++) {
                int c = wn * 32 + nt * 8 + cq;
                sMsg[wm * Cn + c] = s0[nt];
                sMsg[wm * Cn + c + 1] = s1[nt];
            }
        }
        __syncthreads();

        // ---- LN1: u = LN(node_h + (msg + 48*b3)/30) -> g_u ----
        if (warp < 2) {
            const int gg = g0 + warp;
            float x[4], sum = 0.f, sq = 0.f;
#pragma unroll
            for (int j = 0; j < 4; j++) {
                int c = lane + 32 * j;
                float m = (sMsg[warp * Cn + c] + 48.f * sB3[c]) * (1.f / 30.f);
                x[j] = node_h[(size_t)gg * Cn + c] + m;
                sum += x[j];
                sq += x[j] * x[j];
            }
#pragma unroll
            for (int off = 16; off; off >>= 1) {
                sum += __shfl_xor_sync(0xffffffffu, sum, off);
                sq += __shfl_xor_sync(0xffffffffu, sq, off);
            }
            float mean = sum * (1.f / Cn);
            float var = sq * (1.f / Cn) - mean * mean;
            float rs = rsqrtf(var + 1e-5f);
#pragma unroll
            for (int j = 0; j < 4; j++) {
                int c = lane + 32 * j;
                g_u[(size_t)gg * Cn + c] = (x[j] - mean) * rs * sLG[c] + sLB[c];
            }
        }
    }
}

// ---------------- final: out = LN(node_h + u@Wu + bu), fp32 ----------------
__global__ void __launch_bounds__(256)
final_kernel(const float* __restrict__ node_h, const float* __restrict__ Wu,
             const float* __restrict__ bu, const float* __restrict__ ln_g,
             const float* __restrict__ ln_b, float* __restrict__ out) {
    extern __shared__ float sWu[];
    __shared__ float sU[8][128];
    int tid = threadIdx.x, lane = tid & 31, warp = tid >> 5;
    for (int i = tid; i < Cn * Cn; i += 256) sWu[i] = Wu[i];
    int g = blockIdx.x * 8 + warp;
#pragma unroll
    for (int j = 0; j < 4; j++) sU[warp][lane + 32 * j] = g_u[(size_t)g * Cn + lane + 32 * j];
    __syncthreads();

    float y[4] = {0.f, 0.f, 0.f, 0.f};
#pragma unroll 4
    for (int k = 0; k < Cn; k++) {
        float uk = sU[warp][k];
#pragma unroll
        for (int j = 0; j < 4; j++) y[j] += uk * sWu[k * Cn + lane + 32 * j];
    }
    float x[4], sum = 0.f, sq = 0.f;
#pragma unroll
    for (int j = 0; j < 4; j++) {
        int c = lane + 32 * j;
        x[j] = node_h[(size_t)g * Cn + c] + y[j] + bu[c];
        sum += x[j];
        sq += x[j] * x[j];
    }
#pragma unroll
    for (int off = 16; off; off >>= 1) {
        sum += __shfl_xor_sync(0xffffffffu, sum, off);
        sq += __shfl_xor_sync(0xffffffffu, sq, off);
    }
    float mean = sum * (1.f / Cn);
    float var = sq * (1.f / Cn) - mean * mean;
    float rs = rsqrtf(var + 1e-5f);
#pragma unroll
    for (int j = 0; j < 4; j++) {
        int c = lane + 32 * j;
        out[(size_t)g * Cn + c] = (x[j] - mean) * rs * ln_g[c] + ln_b[c];
    }
}

// ---------------- launch ----------------
extern "C" void kernel_launch(void* const* d_in, const int* in_sizes, int n_in,
                              void* d_out, int out_size) {
    const float* node_h = (const float*)d_in[0];
    const float* edge_h = (const float*)d_in[1];
    const void* edge_index = d_in[2];
    const float* W1 = (const float*)d_in[3];
    const float* b1 = (const float*)d_in[4];
    const float* W2 = (const float*)d_in[5];
    const float* b2 = (const float*)d_in[6];
    const float* W3 = (const float*)d_in[7];
    const float* b3 = (const float*)d_in[8];
    const float* Wu = (const float*)d_in[9];
    const float* bu = (const float*)d_in[10];
    const float* ln_g = (const float*)d_in[11];
    const float* ln_b = (const float*)d_in[12];
    float* out = (float*)d_out;

    cudaFuncSetAttribute(pij_kernel, cudaFuncAttributeMaxDynamicSharedMemorySize, 131072);
    cudaFuncSetAttribute(mlp_kernel, cudaFuncAttributeMaxDynamicSharedMemorySize, SMEM_MLP);
    cudaFuncSetAttribute(final_kernel, cudaFuncAttributeMaxDynamicSharedMemorySize, 65536);

    prep_kernel<<<192, 256>>>(W1, W2, W3, (const unsigned*)edge_index);
    pij_kernel<<<128, 256, 131072>>>(node_h, W1, b1);
    mlp_kernel<<<148, 256, SMEM_MLP>>>(node_h, edge_h, edge_index, b2, b3, ln_g, ln_b);
    final_kernel<<<Bn * Nn / 8, 256, 65536>>>(node_h, Wu, bu, ln_g, ln_b, out);
}

// round 5
// speedup vs baseline: 1.8662x; 1.2634x over previous
#include <cuda_runtime.h>
#include <cuda_bf16.h>
#include <stdint.h>

#define Bn 2
#define Nn 2048
#define Kn 48
#define Cn 128
#define TILES (Bn * Nn / 2)

// ---------------- device scratch ----------------
__device__ __nv_bfloat16 g_W1c[128 * 128];   // [n][k] = W1[256+k][n]
__device__ __nv_bfloat16 g_W2t[128 * 128];
__device__ __nv_bfloat16 g_W3t[128 * 128];
__device__ __nv_bfloat16 g_edge_bf[(size_t)Bn * Nn * Kn * Cn];  // 50 MB bf16 edges
__device__ float g_Pi[Bn * Nn * Cn];         // node_h @ W1[0:128] + b1
__device__ float g_Pj[Bn * Nn * Cn];         // node_h @ W1[128:256]
__device__ float g_u[Bn * Nn * Cn];
__device__ int   g_is64;

// ---------------- helpers ----------------
__device__ __forceinline__ uint32_t smem_u32(const void* p) {
    uint32_t a;
    asm("{ .reg .u64 t; cvta.to.shared.u64 t, %1; cvt.u32.u64 %0, t; }" : "=r"(a) : "l"(p));
    return a;
}
__device__ __forceinline__ unsigned pk2(float a, float b) {
    __nv_bfloat162 t = __floats2bfloat162_rn(a, b);
    return *reinterpret_cast<unsigned*>(&t);
}
__device__ __forceinline__ float gelu_erf(float x) {
    return 0.5f * x * (1.0f + erff(x * 0.70710678118654752f));
}
__device__ __forceinline__ void mma16816(float c[4], const uint32_t a[4], const uint32_t b[2]) {
    asm volatile(
        "mma.sync.aligned.m16n8k16.row.col.f32.bf16.bf16.f32 "
        "{%0,%1,%2,%3},{%4,%5,%6,%7},{%8,%9},{%0,%1,%2,%3};"
        : "+f"(c[0]), "+f"(c[1]), "+f"(c[2]), "+f"(c[3])
        : "r"(a[0]), "r"(a[1]), "r"(a[2]), "r"(a[3]), "r"(b[0]), "r"(b[1]));
}
__device__ __forceinline__ void ldsm4(uint32_t r[4], uint32_t addr) {
    asm volatile("ldmatrix.sync.aligned.m8n8.x4.shared.b16 {%0,%1,%2,%3}, [%4];"
                 : "=r"(r[0]), "=r"(r[1]), "=r"(r[2]), "=r"(r[3]) : "r"(addr));
}
__device__ __forceinline__ void cp16(uint32_t dst, const void* src) {
    asm volatile("cp.async.cg.shared.global [%0], [%1], 16;" :: "r"(dst), "l"(src) : "memory");
}
#define CP_COMMIT() asm volatile("cp.async.commit_group;" ::: "memory")
#define CP_WAIT(N)  asm volatile("cp.async.wait_group %0;" :: "n"(N) : "memory")

// XOR-swizzled bf16 tile: 256B rows, 16B chunks; conflict-free ldmatrix, no padding
__device__ __forceinline__ uint32_t phys(int row, int chunk) {
    return (uint32_t)(row * 256 + ((chunk ^ (row & 7)) << 4));
}

// ---------------- prep: weight transposes + idx dtype detect ----------------
__global__ void prep_kernel(const float* __restrict__ W1, const float* __restrict__ W2,
                            const float* __restrict__ W3, const unsigned* __restrict__ idxw) {
    int i = blockIdx.x * 256 + threadIdx.x;
    if (i < 16384) {
        int n = i >> 7, k = i & 127;
        g_W1c[i] = __float2bfloat16_rn(W1[(256 + k) * 128 + n]);
    } else if (i < 32768) {
        int j = i - 16384, n = j >> 7, k = j & 127;
        g_W2t[j] = __float2bfloat16_rn(W2[k * 128 + n]);
    } else if (i < 49152) {
        int j = i - 32768, n = j >> 7, k = j & 127;
        g_W3t[j] = __float2bfloat16_rn(W3[k * 128 + n]);
    }
    if (blockIdx.x == 0 && threadIdx.x == 0) {
        int is64 = 1;
#pragma unroll 1
        for (int t = 1; t < 128; t += 2)
            if (idxw[t] != 0u) { is64 = 0; break; }
        g_is64 = is64;
    }
}

// ---------------- edge fp32 -> bf16 global convert ----------------
__global__ void __launch_bounds__(256)
conv_kernel(const float4* __restrict__ src) {
    const size_t total = (size_t)Bn * Nn * Kn * 32;   // float4 count
    size_t step = (size_t)gridDim.x * 256;
    for (size_t i = (size_t)blockIdx.x * 256 + threadIdx.x; i < total; i += step) {
        float4 v = src[i];
        uint2 p;
        p.x = pk2(v.x, v.y);
        p.y = pk2(v.z, v.w);
        *(uint2*)(g_edge_bf + i * 4) = p;
    }
}

// ---------------- Pi/Pj precompute (fp32, register-blocked) ----------------
// 128 CTAs x 32 rows; warp = 4 rows, thread = 4 cols
__global__ void __launch_bounds__(256)
pij_kernel(const float* __restrict__ node_h, const float* __restrict__ W1,
           const float* __restrict__ b1) {
    extern __shared__ float sw[];           // Wa 16384 | Wb 16384 | X 4096
    float* sWa = sw;
    float* sWb = sw + 16384;
    float* sX  = sw + 32768;
    int tid = threadIdx.x, lane = tid & 31, warp = tid >> 5;
    for (int i = tid; i < 16384; i += 256) {
        sWa[i] = W1[i];
        sWb[i] = W1[16384 + i];
    }
    int rbase = blockIdx.x * 32;
    for (int i = tid; i < 4096; i += 256)
        sX[i] = node_h[(size_t)rbase * 128 + i];
    __syncthreads();

    int c0 = lane * 4;
    float yi[4][4], yj[4][4];
#pragma unroll
    for (int r = 0; r < 4; r++)
#pragma unroll
        for (int j = 0; j < 4; j++) { yi[r][j] = 0.f; yj[r][j] = 0.f; }

#pragma unroll 4
    for (int k = 0; k < 128; k++) {
        float4 wa = *(const float4*)(sWa + k * 128 + c0);
        float4 wb = *(const float4*)(sWb + k * 128 + c0);
#pragma unroll
        for (int r = 0; r < 4; r++) {
            float x = sX[(warp * 4 + r) * 128 + k];
            yi[r][0] += x * wa.x; yi[r][1] += x * wa.y;
            yi[r][2] += x * wa.z; yi[r][3] += x * wa.w;
            yj[r][0] += x * wb.x; yj[r][1] += x * wb.y;
            yj[r][2] += x * wb.z; yj[r][3] += x * wb.w;
        }
    }
    float4 bv = *(const float4*)(b1 + c0);
#pragma unroll
    for (int r = 0; r < 4; r++) {
        size_t row = (size_t)rbase + warp * 4 + r;
        float4 oi;
        oi.x = yi[r][0] + bv.x; oi.y = yi[r][1] + bv.y;
        oi.z = yi[r][2] + bv.z; oi.w = yi[r][3] + bv.w;
        *(float4*)(g_Pi + row * 128 + c0) = oi;
        float4 oj; oj.x = yj[r][0]; oj.y = yj[r][1]; oj.z = yj[r][2]; oj.w = yj[r][3];
        *(float4*)(g_Pj + row * 128 + c0) = oj;
    }
}

// ---------------- persistent edge-MLP kernel, cp.async pipelined ----------------
#define OFF_E0  0
#define OFF_E1  24576
#define OFF_H   49152
#define OFF_PJ  73728          // 96 rows x 132 floats (528B rows)
#define OFF_W1  124416
#define OFF_W2  157184
#define OFF_W3  189952
#define OFF_B2  222720
#define OFF_B3  223232
#define OFF_LG  223744
#define OFF_LB  224256
#define OFF_PI  224768         // 2 x 128 floats
#define OFF_MSG 225792         // 2 x 128 floats
#define SMEM_MLP 226816

__global__ void __launch_bounds__(256, 1)
mlp_kernel(const float* __restrict__ node_h, const void* __restrict__ edge_index,
           const float* __restrict__ b2, const float* __restrict__ b3,
           const float* __restrict__ ln_g, const float* __restrict__ ln_b) {
    extern __shared__ char smem[];
    const uint32_t sb = smem_u32(smem);
    float* sPJ  = (float*)(smem + OFF_PJ);
    float* sB2  = (float*)(smem + OFF_B2);
    float* sB3  = (float*)(smem + OFF_B3);
    float* sLG  = (float*)(smem + OFF_LG);
    float* sLB  = (float*)(smem + OFF_LB);
    float* sPi  = (float*)(smem + OFF_PI);
    float* sMsg = (float*)(smem + OFF_MSG);

    const int tid = threadIdx.x, lane = tid & 31, warp = tid >> 5;
    const int wm = warp >> 2, wn = warp & 3;
    const int r0 = wm * 48;
    const int cq = (lane & 3) * 2;

    // stage weights (swizzled) + small vectors
    for (int i = tid; i < 128 * 16; i += 256) {
        int n = i >> 4, ch = (i & 15);
        uint32_t d = phys(n, ch);
        *(uint4*)(smem + OFF_W1 + d) = *(const uint4*)(g_W1c + n * 128 + ch * 8);
        *(uint4*)(smem + OFF_W2 + d) = *(const uint4*)(g_W2t + n * 128 + ch * 8);
        *(uint4*)(smem + OFF_W3 + d) = *(const uint4*)(g_W3t + n * 128 + ch * 8);
    }
    if (tid < 128) {
        sB2[tid] = b2[tid]; sB3[tid] = b3[tid];
        sLG[tid] = ln_g[tid]; sLB[tid] = ln_b[tid];
    }
    const int is64 = g_is64;
    const long long* idx64 = (const long long*)edge_index;
    const int* idx32 = (const int*)edge_index;

    auto issue_edges = [&](uint32_t ebuf, int tile) {
        size_t rbase = (size_t)tile * 96;
#pragma unroll 1
        for (int i = tid; i < 1536; i += 256) {
            int row = i >> 4, ch = i & 15;
            cp16(sb + ebuf + phys(row, ch), g_edge_bf + (rbase + row) * 128 + ch * 8);
        }
    };
    auto issue_pj = [&](int tile) {
        size_t ibase = (size_t)tile * 96;
        int bbn = (tile * 2) >> 11;
#pragma unroll 1
        for (int i = tid; i < 3072; i += 256) {
            int row = i >> 5, ch = i & 31;
            int j = is64 ? (int)idx64[ibase + row] : idx32[ibase + row];
            cp16(sb + OFF_PJ + row * 528 + ch * 16,
                 g_Pj + ((size_t)bbn * Nn + j) * 128 + ch * 4);
        }
    };

    float acc[3][4][4];
    auto run_mma = [&](uint32_t aOff, uint32_t wOff) {
#pragma unroll
        for (int mt = 0; mt < 3; mt++)
#pragma unroll
            for (int nt = 0; nt < 4; nt++)
#pragma unroll
                for (int q = 0; q < 4; q++) acc[mt][nt][q] = 0.f;
#pragma unroll
        for (int kt = 0; kt < 8; kt++) {
            int ch = kt * 2 + (lane >> 4);
            uint32_t rb[2][4];
#pragma unroll
            for (int j = 0; j < 2; j++)
                ldsm4(rb[j], sb + wOff + phys(wn * 32 + j * 16 + (lane & 15), ch));
#pragma unroll
            for (int mt = 0; mt < 3; mt++) {
                uint32_t ra[4];
                ldsm4(ra, sb + aOff + phys(r0 + mt * 16 + (lane & 15), ch));
#pragma unroll
                for (int j = 0; j < 2; j++)
#pragma unroll
                    for (int h = 0; h < 2; h++) {
                        uint32_t bbf[2] = { rb[j][h], rb[j][2 + h] };
                        mma16816(acc[mt][j * 2 + h], ra, bbf);
                    }
            }
        }
    };

    // ---- initial prefetch: tile t0 ----
    int t = blockIdx.x;
    issue_edges(OFF_E0, t); CP_COMMIT();       // A(t0)
    issue_pj(t);            CP_COMMIT();       // B(t0)

    int it = 0;
#pragma unroll 1
    for (; t < TILES; t += gridDim.x, it++) {
        const uint32_t eCur = (it & 1) ? OFF_E1 : OFF_E0;
        const uint32_t eNxt = (it & 1) ? OFF_E0 : OFF_E1;
        const int g0 = t * 2;
        const int tn = t + gridDim.x;
        const bool hn = tn < TILES;

        // a: prefetch next edges; stage Pi rows for this tile
        if (hn) issue_edges(eNxt, tn);
        CP_COMMIT();                            // A(next)
        if (tid < 256) sPi[tid] = g_Pi[(size_t)g0 * 128 + tid];
        CP_WAIT(2);                             // edges(cur) ready
        __syncthreads();

        // b: layer 1 MMA (edge part)
        run_mma(eCur, OFF_W1);

        // c: PJ(cur) ready
        CP_WAIT(1);
        __syncthreads();

        // d: epi1 = gelu(acc + Pi + Pj) -> H
#pragma unroll
        for (int mt = 0; mt < 3; mt++) {
            int r = r0 + mt * 16 + (lane >> 2);
#pragma unroll
            for (int nt = 0; nt < 4; nt++) {
                int c = wn * 32 + nt * 8 + cq;
                float pix = sPi[wm * 128 + c], piy = sPi[wm * 128 + c + 1];
                float h00 = acc[mt][nt][0] + pix + sPJ[r * 132 + c];
                float h01 = acc[mt][nt][1] + piy + sPJ[r * 132 + c + 1];
                float h10 = acc[mt][nt][2] + pix + sPJ[(r + 8) * 132 + c];
                float h11 = acc[mt][nt][3] + piy + sPJ[(r + 8) * 132 + c + 1];
                uint32_t base = phys(r, c >> 3) + (c & 7) * 2;
                uint32_t base8 = phys(r + 8, c >> 3) + (c & 7) * 2;
                *(unsigned*)(smem + OFF_H + base)  = pk2(gelu_erf(h00), gelu_erf(h01));
                *(unsigned*)(smem + OFF_H + base8) = pk2(gelu_erf(h10), gelu_erf(h11));
            }
        }
        __syncthreads();

        // e: prefetch next PJ
        if (hn) issue_pj(tn);
        CP_COMMIT();                            // B(next)

        // f: layer 2 MMA + epi2 -> eCur (h2)
        run_mma(OFF_H, OFF_W2);
#pragma unroll
        for (int mt = 0; mt < 3; mt++) {
            int r = r0 + mt * 16 + (lane >> 2);
#pragma unroll
            for (int nt = 0; nt < 4; nt++) {
                int c = wn * 32 + nt * 8 + cq;
                float bb0 = sB2[c], bb1 = sB2[c + 1];
                uint32_t base = phys(r, c >> 3) + (c & 7) * 2;
                uint32_t base8 = phys(r + 8, c >> 3) + (c & 7) * 2;
                *(unsigned*)(smem + eCur + base) =
                    pk2(gelu_erf(acc[mt][nt][0] + bb0), gelu_erf(acc[mt][nt][1] + bb1));
                *(unsigned*)(smem + eCur + base8) =
                    pk2(gelu_erf(acc[mt][nt][2] + bb0), gelu_erf(acc[mt][nt][3] + bb1));
            }
        }
        __syncthreads();

        // g: layer 3 MMA + aggregation + LN1
        run_mma(eCur, OFF_W3);
        float s0[4], s1[4];
#pragma unroll
        for (int nt = 0; nt < 4; nt++) {
            s0[nt] = acc[0][nt][0] + acc[0][nt][2] + acc[1][nt][0] + acc[1][nt][2] +
                     acc[2][nt][0] + acc[2][nt][2];
            s1[nt] = acc[0][nt][1] + acc[0][nt][3] + acc[1][nt][1] + acc[1][nt][3] +
                     acc[2][nt][1] + acc[2][nt][3];
        }
#pragma unroll
        for (int off = 4; off < 32; off <<= 1)
#pragma unroll
            for (int nt = 0; nt < 4; nt++) {
                s0[nt] += __shfl_xor_sync(0xffffffffu, s0[nt], off);
                s1[nt] += __shfl_xor_sync(0xffffffffu, s1[nt], off);
            }
        if (lane < 4) {
#pragma unroll
            for (int nt = 0; nt < 4; nt++) {
                int c = wn * 32 + nt * 8 + cq;
                sMsg[wm * Cn + c] = s0[nt];
                sMsg[wm * Cn + c + 1] = s1[nt];
            }
        }
        __syncthreads();

        if (warp < 2) {
            const int gg = g0 + warp;
            float x[4], sum = 0.f, sq = 0.f;
#pragma unroll
            for (int j = 0; j < 4; j++) {
                int c = lane + 32 * j;
                float m = (sMsg[warp * Cn + c] + 48.f * sB3[c]) * (1.f / 30.f);
                x[j] = node_h[(size_t)gg * Cn + c] + m;
                sum += x[j];
                sq += x[j] * x[j];
            }
#pragma unroll
            for (int off = 16; off; off >>= 1) {
                sum += __shfl_xor_sync(0xffffffffu, sum, off);
                sq += __shfl_xor_sync(0xffffffffu, sq, off);
            }
            float mean = sum * (1.f / Cn);
            float var = sq * (1.f / Cn) - mean * mean;
            float rs = rsqrtf(var + 1e-5f);
#pragma unroll
            for (int j = 0; j < 4; j++) {
                int c = lane + 32 * j;
                g_u[(size_t)gg * Cn + c] = (x[j] - mean) * rs * sLG[c] + sLB[c];
            }
        }
        // next iteration's barrier (after wait) separates LN1/sMsg/L3 reads from reuse
    }
}

// ---------------- final: out = LN(node_h + u@Wu + bu), fp32, 32 rows/CTA ----------------
__global__ void __launch_bounds__(256)
final_kernel(const float* __restrict__ node_h, const float* __restrict__ Wu,
             const float* __restrict__ bu, const float* __restrict__ ln_g,
             const float* __restrict__ ln_b, float* __restrict__ out) {
    extern __shared__ float sh[];            // Wu 16384 | U 4096
    float* sWu = sh;
    float* sU  = sh + 16384;
    int tid = threadIdx.x, lane = tid & 31, warp = tid >> 5;
    for (int i = tid; i < 16384; i += 256) sWu[i] = Wu[i];
    int rbase = blockIdx.x * 32;
    for (int i = tid; i < 4096; i += 256) sU[i] = g_u[(size_t)rbase * 128 + i];
    __syncthreads();

    int c0 = lane * 4;
    float y[4][4];
#pragma unroll
    for (int r = 0; r < 4; r++)
#pragma unroll
        for (int j = 0; j < 4; j++) y[r][j] = 0.f;
#pragma unroll 4
    for (int k = 0; k < 128; k++) {
        float4 w = *(const float4*)(sWu + k * 128 + c0);
#pragma unroll
        for (int r = 0; r < 4; r++) {
            float u = sU[(warp * 4 + r) * 128 + k];
            y[r][0] += u * w.x; y[r][1] += u * w.y;
            y[r][2] += u * w.z; y[r][3] += u * w.w;
        }
    }
    float4 bv = *(const float4*)(bu + c0);
    float4 gv = *(const float4*)(ln_g + c0);
    float4 lv = *(const float4*)(ln_b + c0);
#pragma unroll
    for (int r = 0; r < 4; r++) {
        size_t row = (size_t)rbase + warp * 4 + r;
        float4 nh = *(const float4*)(node_h + row * 128 + c0);
        float x0 = nh.x + y[r][0] + bv.x;
        float x1 = nh.y + y[r][1] + bv.y;
        float x2 = nh.z + y[r][2] + bv.z;
        float x3 = nh.w + y[r][3] + bv.w;
        float sum = x0 + x1 + x2 + x3;
        float sq = x0 * x0 + x1 * x1 + x2 * x2 + x3 * x3;
#pragma unroll
        for (int off = 16; off; off >>= 1) {
            sum += __shfl_xor_sync(0xffffffffu, sum, off);
            sq += __shfl_xor_sync(0xffffffffu, sq, off);
        }
        float mean = sum * (1.f / 128.f);
        float var = sq * (1.f / 128.f) - mean * mean;
        float rs = rsqrtf(var + 1e-5f);
        float4 o;
        o.x = (x0 - mean) * rs * gv.x + lv.x;
        o.y = (x1 - mean) * rs * gv.y + lv.y;
        o.z = (x2 - mean) * rs * gv.z + lv.z;
        o.w = (x3 - mean) * rs * gv.w + lv.w;
        *(float4*)(out + row * 128 + c0) = o;
    }
}

// ---------------- launch ----------------
extern "C" void kernel_launch(void* const* d_in, const int* in_sizes, int n_in,
                              void* d_out, int out_size) {
    const float* node_h = (const float*)d_in[0];
    const float* edge_h = (const float*)d_in[1];
    const void* edge_index = d_in[2];
    const float* W1 = (const float*)d_in[3];
    const float* b1 = (const float*)d_in[4];
    const float* W2 = (const float*)d_in[5];
    const float* b2 = (const float*)d_in[6];
    const float* W3 = (const float*)d_in[7];
    const float* b3 = (const float*)d_in[8];
    const float* Wu = (const float*)d_in[9];
    const float* bu = (const float*)d_in[10];
    const float* ln_g = (const float*)d_in[11];
    const float* ln_b = (const float*)d_in[12];
    float* out = (float*)d_out;

    cudaFuncSetAttribute(pij_kernel, cudaFuncAttributeMaxDynamicSharedMemorySize, 147456);
    cudaFuncSetAttribute(mlp_kernel, cudaFuncAttributeMaxDynamicSharedMemorySize, SMEM_MLP);
    cudaFuncSetAttribute(final_kernel, cudaFuncAttributeMaxDynamicSharedMemorySize, 81920);

    prep_kernel<<<192, 256>>>(W1, W2, W3, (const unsigned*)edge_index);
    conv_kernel<<<2048, 256>>>((const float4*)edge_h);
    pij_kernel<<<128, 256, 147456>>>(node_h, W1, b1);
    mlp_kernel<<<148, 256, SMEM_MLP>>>(node_h, edge_index, b2, b3, ln_g, ln_b);
    final_kernel<<<128, 256, 81920>>>(node_h, Wu, bu, ln_g, ln_b, out);
}

// round 6
// speedup vs baseline: 2.0591x; 1.1034x over previous
#include <cuda_runtime.h>
#include <cuda_bf16.h>
#include <stdint.h>

#define Bn 2
#define Nn 2048
#define Kn 48
#define Cn 128
#define TILES (Bn * Nn / 2)

// ---------------- device scratch ----------------
__device__ __nv_bfloat16 g_W1c[128 * 128];   // [n][k] = W1[256+k][n]
__device__ __nv_bfloat16 g_W2t[128 * 128];
__device__ __nv_bfloat16 g_W3t[128 * 128];
__device__ __nv_bfloat16 g_edge_bf[(size_t)Bn * Nn * Kn * Cn];  // 50 MB bf16 edges
__device__ float g_Pi[Bn * Nn * Cn];         // node_h @ W1[0:128] + b1
__device__ float g_Pj[Bn * Nn * Cn];         // node_h @ W1[128:256]
__device__ float g_u[Bn * Nn * Cn];
__device__ int   g_is64;

// ---------------- helpers ----------------
__device__ __forceinline__ uint32_t smem_u32(const void* p) {
    uint32_t a;
    asm("{ .reg .u64 t; cvta.to.shared.u64 t, %1; cvt.u32.u64 %0, t; }" : "=r"(a) : "l"(p));
    return a;
}
__device__ __forceinline__ unsigned pk2(float a, float b) {
    __nv_bfloat162 t = __floats2bfloat162_rn(a, b);
    return *reinterpret_cast<unsigned*>(&t);
}
__device__ __forceinline__ float gelu_erf(float x) {
    return 0.5f * x * (1.0f + erff(x * 0.70710678118654752f));
}
__device__ __forceinline__ void mma16816(float c[4], const uint32_t a[4], const uint32_t b[2]) {
    asm volatile(
        "mma.sync.aligned.m16n8k16.row.col.f32.bf16.bf16.f32 "
        "{%0,%1,%2,%3},{%4,%5,%6,%7},{%8,%9},{%0,%1,%2,%3};"
        : "+f"(c[0]), "+f"(c[1]), "+f"(c[2]), "+f"(c[3])
        : "r"(a[0]), "r"(a[1]), "r"(a[2]), "r"(a[3]), "r"(b[0]), "r"(b[1]));
}
__device__ __forceinline__ void ldsm4(uint32_t r[4], uint32_t addr) {
    asm volatile("ldmatrix.sync.aligned.m8n8.x4.shared.b16 {%0,%1,%2,%3}, [%4];"
                 : "=r"(r[0]), "=r"(r[1]), "=r"(r[2]), "=r"(r[3]) : "r"(addr));
}
__device__ __forceinline__ void cp16(uint32_t dst, const void* src) {
    asm volatile("cp.async.cg.shared.global [%0], [%1], 16;" :: "r"(dst), "l"(src) : "memory");
}
#define CP_COMMIT() asm volatile("cp.async.commit_group;" ::: "memory")
#define CP_WAIT(N)  asm volatile("cp.async.wait_group %0;" :: "n"(N) : "memory")

// XOR-swizzled bf16 tile: 256B rows, 16B chunks; conflict-free ldmatrix, no padding
__device__ __forceinline__ uint32_t phys(int row, int chunk) {
    return (uint32_t)(row * 256 + ((chunk ^ (row & 7)) << 4));
}

// ---------------- prep: weight transposes + idx dtype detect ----------------
__global__ void prep_kernel(const float* __restrict__ W1, const float* __restrict__ W2,
                            const float* __restrict__ W3, const unsigned* __restrict__ idxw) {
    int i = blockIdx.x * 256 + threadIdx.x;
    if (i < 16384) {
        int n = i >> 7, k = i & 127;
        g_W1c[i] = __float2bfloat16_rn(W1[(256 + k) * 128 + n]);
    } else if (i < 32768) {
        int j = i - 16384, n = j >> 7, k = j & 127;
        g_W2t[j] = __float2bfloat16_rn(W2[k * 128 + n]);
    } else if (i < 49152) {
        int j = i - 32768, n = j >> 7, k = j & 127;
        g_W3t[j] = __float2bfloat16_rn(W3[k * 128 + n]);
    }
    if (blockIdx.x == 0 && threadIdx.x == 0) {
        int is64 = 1;
#pragma unroll 1
        for (int t = 1; t < 128; t += 2)
            if (idxw[t] != 0u) { is64 = 0; break; }
        g_is64 = is64;
    }
}

// ---------------- edge fp32 -> bf16 global convert ----------------
__global__ void __launch_bounds__(256)
conv_kernel(const float4* __restrict__ src) {
    const size_t total = (size_t)Bn * Nn * Kn * 32;   // float4 count
    size_t step = (size_t)gridDim.x * 256;
    for (size_t i = (size_t)blockIdx.x * 256 + threadIdx.x; i < total; i += step) {
        float4 v = src[i];
        uint2 p;
        p.x = pk2(v.x, v.y);
        p.y = pk2(v.z, v.w);
        *(uint2*)(g_edge_bf + i * 4) = p;
    }
}

// ---------------- Pi/Pj precompute (fp32, register-blocked) ----------------
__global__ void __launch_bounds__(256)
pij_kernel(const float* __restrict__ node_h, const float* __restrict__ W1,
           const float* __restrict__ b1) {
    extern __shared__ float sw[];           // Wa 16384 | Wb 16384 | X 4096
    float* sWa = sw;
    float* sWb = sw + 16384;
    float* sX  = sw + 32768;
    int tid = threadIdx.x, lane = tid & 31, warp = tid >> 5;
    for (int i = tid; i < 16384; i += 256) {
        sWa[i] = W1[i];
        sWb[i] = W1[16384 + i];
    }
    int rbase = blockIdx.x * 32;
    for (int i = tid; i < 4096; i += 256)
        sX[i] = node_h[(size_t)rbase * 128 + i];
    __syncthreads();

    int c0 = lane * 4;
    float yi[4][4], yj[4][4];
#pragma unroll
    for (int r = 0; r < 4; r++)
#pragma unroll
        for (int j = 0; j < 4; j++) { yi[r][j] = 0.f; yj[r][j] = 0.f; }

#pragma unroll 4
    for (int k = 0; k < 128; k++) {
        float4 wa = *(const float4*)(sWa + k * 128 + c0);
        float4 wb = *(const float4*)(sWb + k * 128 + c0);
#pragma unroll
        for (int r = 0; r < 4; r++) {
            float x = sX[(warp * 4 + r) * 128 + k];
            yi[r][0] += x * wa.x; yi[r][1] += x * wa.y;
            yi[r][2] += x * wa.z; yi[r][3] += x * wa.w;
            yj[r][0] += x * wb.x; yj[r][1] += x * wb.y;
            yj[r][2] += x * wb.z; yj[r][3] += x * wb.w;
        }
    }
    float4 bv = *(const float4*)(b1 + c0);
#pragma unroll
    for (int r = 0; r < 4; r++) {
        size_t row = (size_t)rbase + warp * 4 + r;
        float4 oi;
        oi.x = yi[r][0] + bv.x; oi.y = yi[r][1] + bv.y;
        oi.z = yi[r][2] + bv.z; oi.w = yi[r][3] + bv.w;
        *(float4*)(g_Pi + row * 128 + c0) = oi;
        float4 oj; oj.x = yj[r][0]; oj.y = yj[r][1]; oj.z = yj[r][2]; oj.w = yj[r][3];
        *(float4*)(g_Pj + row * 128 + c0) = oj;
    }
}

// ---------------- persistent edge-MLP kernel, 512 threads, cp.async pipelined ----------------
#define OFF_E0  0
#define OFF_E1  24576
#define OFF_H   49152
#define OFF_PJ  73728          // 96 rows x 132 floats (528B rows)
#define OFF_W1  124416
#define OFF_W2  157184
#define OFF_W3  189952
#define OFF_B2  222720
#define OFF_B3  223232
#define OFF_LG  223744
#define OFF_LB  224256
#define OFF_PI  224768         // 2 x 128 floats
#define OFF_MSG 225792         // 2 x 128 floats
#define SMEM_MLP 226816
#define NTHR 512

__global__ void __launch_bounds__(NTHR, 1)
mlp_kernel(const float* __restrict__ node_h, const void* __restrict__ edge_index,
           const float* __restrict__ b2, const float* __restrict__ b3,
           const float* __restrict__ ln_g, const float* __restrict__ ln_b) {
    extern __shared__ char smem[];
    const uint32_t sb = smem_u32(smem);
    float* sPJ  = (float*)(smem + OFF_PJ);
    float* sB2  = (float*)(smem + OFF_B2);
    float* sB3  = (float*)(smem + OFF_B3);
    float* sLG  = (float*)(smem + OFF_LG);
    float* sLB  = (float*)(smem + OFF_LB);
    float* sPi  = (float*)(smem + OFF_PI);
    float* sMsg = (float*)(smem + OFF_MSG);

    const int tid = threadIdx.x, lane = tid & 31, warp = tid >> 5;
    const int wm = warp >> 3;                 // 0/1 : node within tile
    const int wn = warp & 7;                  // 0..7 : 16-col group
    const int r0 = wm * 48;
    const int cq = (lane & 3) * 2;

    // stage weights (swizzled) + small vectors
    for (int i = tid; i < 128 * 16; i += NTHR) {
        int n = i >> 4, ch = (i & 15);
        uint32_t d = phys(n, ch);
        *(uint4*)(smem + OFF_W1 + d) = *(const uint4*)(g_W1c + n * 128 + ch * 8);
        *(uint4*)(smem + OFF_W2 + d) = *(const uint4*)(g_W2t + n * 128 + ch * 8);
        *(uint4*)(smem + OFF_W3 + d) = *(const uint4*)(g_W3t + n * 128 + ch * 8);
    }
    if (tid < 128) {
        sB2[tid] = b2[tid]; sB3[tid] = b3[tid];
        sLG[tid] = ln_g[tid]; sLB[tid] = ln_b[tid];
    }
    const int is64 = g_is64;
    const long long* idx64 = (const long long*)edge_index;
    const int* idx32 = (const int*)edge_index;

    auto issue_edges = [&](uint32_t ebuf, int tile) {
        size_t rbase = (size_t)tile * 96;
#pragma unroll 1
        for (int i = tid; i < 1536; i += NTHR) {
            int row = i >> 4, ch = i & 15;
            cp16(sb + ebuf + phys(row, ch), g_edge_bf + (rbase + row) * 128 + ch * 8);
        }
    };
    auto issue_pj = [&](int tile) {
        size_t ibase = (size_t)tile * 96;
        int bbn = (tile * 2) >> 11;
#pragma unroll 1
        for (int i = tid; i < 3072; i += NTHR) {
            int row = i >> 5, ch = i & 31;
            int j = is64 ? (int)idx64[ibase + row] : idx32[ibase + row];
            cp16(sb + OFF_PJ + row * 528 + ch * 16,
                 g_Pj + ((size_t)bbn * Nn + j) * 128 + ch * 4);
        }
    };

    float acc[3][2][4];
    auto run_mma = [&](uint32_t aOff, uint32_t wOff) {
#pragma unroll
        for (int mt = 0; mt < 3; mt++)
#pragma unroll
            for (int nt = 0; nt < 2; nt++)
#pragma unroll
                for (int q = 0; q < 4; q++) acc[mt][nt][q] = 0.f;
#pragma unroll
        for (int kt = 0; kt < 8; kt++) {
            int ch = kt * 2 + (lane >> 4);
            uint32_t rb[4];
            ldsm4(rb, sb + wOff + phys(wn * 16 + (lane & 15), ch));
#pragma unroll
            for (int mt = 0; mt < 3; mt++) {
                uint32_t ra[4];
                ldsm4(ra, sb + aOff + phys(r0 + mt * 16 + (lane & 15), ch));
#pragma unroll
                for (int h = 0; h < 2; h++) {
                    uint32_t bbf[2] = { rb[h], rb[2 + h] };
                    mma16816(acc[mt][h], ra, bbf);
                }
            }
        }
    };

    // ---- initial prefetch: tile t0 ----
    int t = blockIdx.x;
    issue_edges(OFF_E0, t); CP_COMMIT();       // A(t0)
    issue_pj(t);            CP_COMMIT();       // B(t0)

    int it = 0;
#pragma unroll 1
    for (; t < TILES; t += gridDim.x, it++) {
        const uint32_t eCur = (it & 1) ? OFF_E1 : OFF_E0;
        const uint32_t eNxt = (it & 1) ? OFF_E0 : OFF_E1;
        const int g0 = t * 2;
        const int tn = t + gridDim.x;
        const bool hn = tn < TILES;

        // a: prefetch next edges; stage Pi rows for this tile
        if (hn) issue_edges(eNxt, tn);
        CP_COMMIT();                            // A(next)
        if (tid < 256) sPi[tid] = g_Pi[(size_t)g0 * 128 + tid];
        CP_WAIT(2);                             // edges(cur) ready
        __syncthreads();

        // b: layer 1 MMA (edge part)
        run_mma(eCur, OFF_W1);

        // c: PJ(cur) ready
        CP_WAIT(1);
        __syncthreads();

        // d: epi1 = gelu(acc + Pi + Pj) -> H
#pragma unroll
        for (int mt = 0; mt < 3; mt++) {
            int r = r0 + mt * 16 + (lane >> 2);
#pragma unroll
            for (int nt = 0; nt < 2; nt++) {
                int c = wn * 16 + nt * 8 + cq;
                float pix = sPi[wm * 128 + c], piy = sPi[wm * 128 + c + 1];
                float h00 = acc[mt][nt][0] + pix + sPJ[r * 132 + c];
                float h01 = acc[mt][nt][1] + piy + sPJ[r * 132 + c + 1];
                float h10 = acc[mt][nt][2] + pix + sPJ[(r + 8) * 132 + c];
                float h11 = acc[mt][nt][3] + piy + sPJ[(r + 8) * 132 + c + 1];
                uint32_t base = phys(r, c >> 3) + (c & 7) * 2;
                uint32_t base8 = phys(r + 8, c >> 3) + (c & 7) * 2;
                *(unsigned*)(smem + OFF_H + base)  = pk2(gelu_erf(h00), gelu_erf(h01));
                *(unsigned*)(smem + OFF_H + base8) = pk2(gelu_erf(h10), gelu_erf(h11));
            }
        }
        __syncthreads();

        // e: prefetch next PJ
        if (hn) issue_pj(tn);
        CP_COMMIT();                            // B(next)

        // f: layer 2 MMA + epi2 -> eCur (h2)
        run_mma(OFF_H, OFF_W2);
#pragma unroll
        for (int mt = 0; mt < 3; mt++) {
            int r = r0 + mt * 16 + (lane >> 2);
#pragma unroll
            for (int nt = 0; nt < 2; nt++) {
                int c = wn * 16 + nt * 8 + cq;
                float bb0 = sB2[c], bb1 = sB2[c + 1];
                uint32_t base = phys(r, c >> 3) + (c & 7) * 2;
                uint32_t base8 = phys(r + 8, c >> 3) + (c & 7) * 2;
                *(unsigned*)(smem + eCur + base) =
                    pk2(gelu_erf(acc[mt][nt][0] + bb0), gelu_erf(acc[mt][nt][1] + bb1));
                *(unsigned*)(smem + eCur + base8) =
                    pk2(gelu_erf(acc[mt][nt][2] + bb0), gelu_erf(acc[mt][nt][3] + bb1));
            }
        }
        __syncthreads();

        // g: layer 3 MMA + aggregation + LN1
        run_mma(eCur, OFF_W3);
        float s0[2], s1[2];
#pragma unroll
        for (int nt = 0; nt < 2; nt++) {
            s0[nt] = acc[0][nt][0] + acc[0][nt][2] + acc[1][nt][0] + acc[1][nt][2] +
                     acc[2][nt][0] + acc[2][nt][2];
            s1[nt] = acc[0][nt][1] + acc[0][nt][3] + acc[1][nt][1] + acc[1][nt][3] +
                     acc[2][nt][1] + acc[2][nt][3];
        }
#pragma unroll
        for (int off = 4; off < 32; off <<= 1)
#pragma unroll
            for (int nt = 0; nt < 2; nt++) {
                s0[nt] += __shfl_xor_sync(0xffffffffu, s0[nt], off);
                s1[nt] += __shfl_xor_sync(0xffffffffu, s1[nt], off);
            }
        if (lane < 4) {
#pragma unroll
            for (int nt = 0; nt < 2; nt++) {
                int c = wn * 16 + nt * 8 + lane * 2;
                sMsg[wm * Cn + c] = s0[nt];
                sMsg[wm * Cn + c + 1] = s1[nt];
            }
        }
        __syncthreads();

        if (warp < 2) {
            const int gg = g0 + warp;
            float x[4], sum = 0.f, sq = 0.f;
#pragma unroll
            for (int j = 0; j < 4; j++) {
                int c = lane + 32 * j;
                float m = (sMsg[warp * Cn + c] + 48.f * sB3[c]) * (1.f / 30.f);
                x[j] = node_h[(size_t)gg * Cn + c] + m;
                sum += x[j];
                sq += x[j] * x[j];
            }
#pragma unroll
            for (int off = 16; off; off >>= 1) {
                sum += __shfl_xor_sync(0xffffffffu, sum, off);
                sq += __shfl_xor_sync(0xffffffffu, sq, off);
            }
            float mean = sum * (1.f / Cn);
            float var = sq * (1.f / Cn) - mean * mean;
            float rs = rsqrtf(var + 1e-5f);
#pragma unroll
            for (int j = 0; j < 4; j++) {
                int c = lane + 32 * j;
                g_u[(size_t)gg * Cn + c] = (x[j] - mean) * rs * sLG[c] + sLB[c];
            }
        }
        // next iteration's post-wait barrier separates LN1/sMsg/L3 reads from reuse
    }
}

// ---------------- final: out = LN(node_h + u@Wu + bu), fp32, 32 rows/CTA ----------------
__global__ void __launch_bounds__(256)
final_kernel(const float* __restrict__ node_h, const float* __restrict__ Wu,
             const float* __restrict__ bu, const float* __restrict__ ln_g,
             const float* __restrict__ ln_b, float* __restrict__ out) {
    extern __shared__ float sh[];            // Wu 16384 | U 4096
    float* sWu = sh;
    float* sU  = sh + 16384;
    int tid = threadIdx.x, lane = tid & 31, warp = tid >> 5;
    for (int i = tid; i < 16384; i += 256) sWu[i] = Wu[i];
    int rbase = blockIdx.x * 32;
    for (int i = tid; i < 4096; i += 256) sU[i] = g_u[(size_t)rbase * 128 + i];
    __syncthreads();

    int c0 = lane * 4;
    float y[4][4];
#pragma unroll
    for (int r = 0; r < 4; r++)
#pragma unroll
        for (int j = 0; j < 4; j++) y[r][j] = 0.f;
#pragma unroll 4
    for (int k = 0; k < 128; k++) {
        float4 w = *(const float4*)(sWu + k * 128 + c0);
#pragma unroll
        for (int r = 0; r < 4; r++) {
            float u = sU[(warp * 4 + r) * 128 + k];
            y[r][0] += u * w.x; y[r][1] += u * w.y;
            y[r][2] += u * w.z; y[r][3] += u * w.w;
        }
    }
    float4 bv = *(const float4*)(bu + c0);
    float4 gv = *(const float4*)(ln_g + c0);
    float4 lv = *(const float4*)(ln_b + c0);
#pragma unroll
    for (int r = 0; r < 4; r++) {
        size_t row = (size_t)rbase + warp * 4 + r;
        float4 nh = *(const float4*)(node_h + row * 128 + c0);
        float x0 = nh.x + y[r][0] + bv.x;
        float x1 = nh.y + y[r][1] + bv.y;
        float x2 = nh.z + y[r][2] + bv.z;
        float x3 = nh.w + y[r][3] + bv.w;
        float sum = x0 + x1 + x2 + x3;
        float sq = x0 * x0 + x1 * x1 + x2 * x2 + x3 * x3;
#pragma unroll
        for (int off = 16; off; off >>= 1) {
            sum += __shfl_xor_sync(0xffffffffu, sum, off);
            sq += __shfl_xor_sync(0xffffffffu, sq, off);
        }
        float mean = sum * (1.f / 128.f);
        float var = sq * (1.f / 128.f) - mean * mean;
        float rs = rsqrtf(var + 1e-5f);
        float4 o;
        o.x = (x0 - mean) * rs * gv.x + lv.x;
        o.y = (x1 - mean) * rs * gv.y + lv.y;
        o.z = (x2 - mean) * rs * gv.z + lv.z;
        o.w = (x3 - mean) * rs * gv.w + lv.w;
        *(float4*)(out + row * 128 + c0) = o;
    }
}

// ---------------- launch ----------------
extern "C" void kernel_launch(void* const* d_in, const int* in_sizes, int n_in,
                              void* d_out, int out_size) {
    const float* node_h = (const float*)d_in[0];
    const float* edge_h = (const float*)d_in[1];
    const void* edge_index = d_in[2];
    const float* W1 = (const float*)d_in[3];
    const float* b1 = (const float*)d_in[4];
    const float* W2 = (const float*)d_in[5];
    const float* b2 = (const float*)d_in[6];
    const float* W3 = (const float*)d_in[7];
    const float* b3 = (const float*)d_in[8];
    const float* Wu = (const float*)d_in[9];
    const float* bu = (const float*)d_in[10];
    const float* ln_g = (const float*)d_in[11];
    const float* ln_b = (const float*)d_in[12];
    float* out = (float*)d_out;

    cudaFuncSetAttribute(pij_kernel, cudaFuncAttributeMaxDynamicSharedMemorySize, 147456);
    cudaFuncSetAttribute(mlp_kernel, cudaFuncAttributeMaxDynamicSharedMemorySize, SMEM_MLP);
    cudaFuncSetAttribute(final_kernel, cudaFuncAttributeMaxDynamicSharedMemorySize, 81920);

    prep_kernel<<<192, 256>>>(W1, W2, W3, (const unsigned*)edge_index);
    conv_kernel<<<2048, 256>>>((const float4*)edge_h);
    pij_kernel<<<128, 256, 147456>>>(node_h, W1, b1);
    mlp_kernel<<<148, NTHR, SMEM_MLP>>>(node_h, edge_index, b2, b3, ln_g, ln_b);
    final_kernel<<<128, 256, 81920>>>(node_h, Wu, bu, ln_g, ln_b, out);
}